// round 16
// baseline (speedup 1.0000x reference)
#include <cuda_runtime.h>
#include <cuda_bf16.h>
#include <cuda_fp16.h>
#include <math.h>

// Problem shape
#define BATCH 512
#define SEQ   256
#define DIM   512
#define NORM  0.044194173824159216f   // 1/sqrt(512)

// Quad-packed fp16 operand layout:
//   Q[row][m], row = kgroup*4 + j, packs halves (v[m][16g+2j], [+1], [+8], [+9])
__device__ uint2 g_MQ[128 * DIM];                     // M quads: [kg*4+j][n]
__device__ uint2 g_XQ[(size_t)BATCH * 128 * SEQ];     // X quads: [b*128 + kg*4+j][m]
__device__ uint2 g_GQ[(size_t)BATCH * 128 * SEQ];     // G quads: [b*128 + ng*4+j][m]
__device__ float g_Y4[(size_t)BATCH * 4 * DIM];       // per-quarter y contributions

extern __shared__ float dynsmem[];

// ---------------------------------------------------------------------------
// helpers
// ---------------------------------------------------------------------------
__device__ __forceinline__ void cp16g(unsigned sa, const void* g) {
    asm volatile("cp.async.cg.shared.global [%0], [%1], 16;" :: "r"(sa), "l"(g));
}
#define CP_COMMIT() asm volatile("cp.async.commit_group;")
#define CP_WAIT1()  asm volatile("cp.async.wait_group 1;")
#define CP_WAIT0()  asm volatile("cp.async.wait_group 0;")

__device__ __forceinline__ void mma_f16(float c[4],
                                        unsigned a0, unsigned a1, unsigned a2, unsigned a3,
                                        unsigned b0, unsigned b1) {
    asm("mma.sync.aligned.m16n8k16.row.col.f32.f16.f16.f32 "
        "{%0,%1,%2,%3}, {%4,%5,%6,%7}, {%8,%9}, {%0,%1,%2,%3};"
        : "+f"(c[0]), "+f"(c[1]), "+f"(c[2]), "+f"(c[3])
        : "r"(a0), "r"(a1), "r"(a2), "r"(a3), "r"(b0), "r"(b1));
}
__device__ __forceinline__ unsigned sm_u32(const void* p) {
    return (unsigned)__cvta_generic_to_shared(p);
}
__device__ __forceinline__ uint2 packq(float a, float b, float c, float d) {
    __half2 lo = __floats2half2_rn(a, b);
    __half2 hi = __floats2half2_rn(c, d);
    uint2 r;
    r.x = *(unsigned*)&lo;
    r.y = *(unsigned*)&hi;
    return r;
}

// ---------------------------------------------------------------------------
// Kernel X2H: X (fp32) -> g_XQ quad-packed fp16.
// ---------------------------------------------------------------------------
__global__ void __launch_bounds__(256) x2h_kernel(const float* __restrict__ X)
{
    __shared__ float s[64][65];
    int tid = threadIdx.x;
    int ktile = blockIdx.x, mtile = blockIdx.y, b = blockIdx.z;

    int r = tid >> 2, c4 = (tid & 3) * 16;
    const float* src = X + ((size_t)b * SEQ + mtile * 64 + r) * DIM + ktile * 64 + c4;
#pragma unroll
    for (int i = 0; i < 4; i++) {
        float4 v = *(const float4*)(src + i * 4);
        s[r][c4 + i * 4 + 0] = v.x;
        s[r][c4 + i * 4 + 1] = v.y;
        s[r][c4 + i * 4 + 2] = v.z;
        s[r][c4 + i * 4 + 3] = v.w;
    }
    __syncthreads();

    int q = tid >> 4, g = q >> 2, j = q & 3;
    int ml = (tid & 15) * 4;
    int kb = g * 16 + 2 * j;
    size_t row = (size_t)b * 128 + (ktile * 4 + g) * 4 + j;
    uint2* dst = g_XQ + row * SEQ + mtile * 64 + ml;
#pragma unroll
    for (int i = 0; i < 4; i++)
        dst[i] = packq(s[ml + i][kb], s[ml + i][kb + 1],
                       s[ml + i][kb + 8], s[ml + i][kb + 9]);
}

// ---------------------------------------------------------------------------
// Kernel A: M = norm * Wq @ Wk^T -> g_MQ quad-packed.  64x64 tiles, grid 8x8.
// ---------------------------------------------------------------------------
__global__ void __launch_bounds__(256) wqwk_kernel(const float* __restrict__ Wq,
                                                   const float* __restrict__ Wk)
{
    __shared__ float As[32][68];
    __shared__ float Bs[32][68];
    __shared__ float Ms[64][65];
    int tid = threadIdx.x;
    int row0 = blockIdx.y * 64;
    int col0 = blockIdx.x * 64;

    int sr = tid >> 2, se = (tid & 3) * 8;
    int tr = tid >> 4, tc = tid & 15;

    float acc[4][4];
#pragma unroll
    for (int i = 0; i < 4; i++)
#pragma unroll
        for (int jj = 0; jj < 4; jj++) acc[i][jj] = 0.0f;

    for (int kt = 0; kt < DIM; kt += 32) {
        float4 q0 = *(const float4*)(Wq + (size_t)(row0 + sr) * DIM + kt + se);
        float4 q1 = *(const float4*)(Wq + (size_t)(row0 + sr) * DIM + kt + se + 4);
        float4 k0 = *(const float4*)(Wk + (size_t)(col0 + sr) * DIM + kt + se);
        float4 k1 = *(const float4*)(Wk + (size_t)(col0 + sr) * DIM + kt + se + 4);
        As[se + 0][sr] = q0.x; As[se + 1][sr] = q0.y;
        As[se + 2][sr] = q0.z; As[se + 3][sr] = q0.w;
        As[se + 4][sr] = q1.x; As[se + 5][sr] = q1.y;
        As[se + 6][sr] = q1.z; As[se + 7][sr] = q1.w;
        Bs[se + 0][sr] = k0.x; Bs[se + 1][sr] = k0.y;
        Bs[se + 2][sr] = k0.z; Bs[se + 3][sr] = k0.w;
        Bs[se + 4][sr] = k1.x; Bs[se + 5][sr] = k1.y;
        Bs[se + 6][sr] = k1.z; Bs[se + 7][sr] = k1.w;
        __syncthreads();
#pragma unroll
        for (int k = 0; k < 32; k++) {
            float4 ra = *(const float4*)(&As[k][tr * 4]);
            float4 rb = *(const float4*)(&Bs[k][tc * 4]);
            float a[4] = {ra.x, ra.y, ra.z, ra.w};
            float b[4] = {rb.x, rb.y, rb.z, rb.w};
#pragma unroll
            for (int i = 0; i < 4; i++)
#pragma unroll
                for (int jj = 0; jj < 4; jj++)
                    acc[i][jj] += a[i] * b[jj];
        }
        __syncthreads();
    }
#pragma unroll
    for (int i = 0; i < 4; i++)
#pragma unroll
        for (int jj = 0; jj < 4; jj++)
            Ms[tr * 4 + i][tc * 4 + jj] = acc[i][jj] * NORM;
    __syncthreads();

    int q = tid >> 4, g = q >> 2, j = q & 3;
    int nl = (tid & 15) * 4;
    int kb = g * 16 + 2 * j;
    size_t rowI = (size_t)((row0 >> 4) + g) * 4 + j;
#pragma unroll
    for (int i = 0; i < 4; i++) {
        int n = nl + i;
        g_MQ[rowI * DIM + col0 + n] = packq(Ms[kb][n], Ms[kb + 1][n],
                                            Ms[kb + 8][n], Ms[kb + 9][n]);
    }
}

// ---------------------------------------------------------------------------
// Kernel B: G = X @ M via fp16 mma (k16), all operands quad-packed.
// CTA 128x128, BK=32, 256 thr, warp tile 64x32. 3-stage cp.async, unrolled.
// launch_bounds(256,2) -> 2 CTAs/SM (smem 49.5KB, regs capped 128).
// ---------------------------------------------------------------------------
#define B_ST 2112   // b64 per stage: A 8*132 + M 8*132
__global__ void __launch_bounds__(256, 2) gemm_G_kernel()
{
    uint2* sm = (uint2*)dynsmem;
    int tid = threadIdx.x;
    int cCol = blockIdx.x;            // 0..3
    int cRow = blockIdx.y;            // 0..1023
    int warp = tid >> 5, lane = tid & 31;
    int wm = warp >> 2, wn = warp & 3;
    int gid = lane >> 2, tig = lane & 3;
    int bb = cRow >> 1, m0 = (cRow & 1) * 128;

    float acc[4][4][4];
#pragma unroll
    for (int mt = 0; mt < 4; mt++)
#pragma unroll
        for (int nt = 0; nt < 4; nt++)
#pragma unroll
            for (int r = 0; r < 4; r++) acc[mt][nt][r] = 0.0f;

    unsigned smb = sm_u32(sm);
    int jr0 = tid >> 6, mp0 = (tid & 63) * 2;
    int jr1 = (tid + 256) >> 6, mp1 = ((tid + 256) & 63) * 2;
    const uint2* XQb = g_XQ + (size_t)bb * 128 * SEQ + m0;
    const uint2* MQb = g_MQ + cCol * 128;

    auto issue = [&](int s, int i) {
        unsigned ab = smb + s * B_ST * 8;
        unsigned mb = ab + 8 * 132 * 8;
        cp16g(ab + (jr0 * 132 + mp0) * 8, XQb + (size_t)(8 * i + jr0) * SEQ + mp0);
        cp16g(mb + (jr0 * 132 + mp0) * 8, MQb + (size_t)(8 * i + jr0) * DIM + mp0);
        cp16g(ab + (jr1 * 132 + mp1) * 8, XQb + (size_t)(8 * i + jr1) * SEQ + mp1);
        cp16g(mb + (jr1 * 132 + mp1) * 8, MQb + (size_t)(8 * i + jr1) * DIM + mp1);
        CP_COMMIT();
    };

    const int NT = 16;
    issue(0, 0);
    issue(1, 1);

#pragma unroll
    for (int i = 0; i < NT; i++) {
        if (i + 1 < NT) CP_WAIT1(); else CP_WAIT0();
        __syncthreads();
        if (i + 2 < NT) issue((i + 2) % 3, i + 2);

        const uint2* A_s = sm + (i % 3) * B_ST;
        const uint2* M_s = A_s + 8 * 132;
#pragma unroll
        for (int gl = 0; gl < 2; gl++) {
            int jb = gl * 4 + tig;
            uint2 va[4], vb[4], w[4];
#pragma unroll
            for (int mt = 0; mt < 4; mt++) {
                int row = wm * 64 + mt * 16 + gid;
                va[mt] = A_s[jb * 132 + row];
                vb[mt] = A_s[jb * 132 + row + 8];
            }
#pragma unroll
            for (int nt = 0; nt < 4; nt++)
                w[nt] = M_s[jb * 132 + wn * 32 + nt * 8 + gid];
#pragma unroll
            for (int mt = 0; mt < 4; mt++)
#pragma unroll
                for (int nt = 0; nt < 4; nt++)
                    mma_f16(acc[mt][nt], va[mt].x, vb[mt].x, va[mt].y, vb[mt].y,
                            w[nt].x, w[nt].y);
        }
    }

#pragma unroll
    for (int mt = 0; mt < 4; mt++)
#pragma unroll
        for (int ntp = 0; ntp < 4; ntp += 2) {
            int g = cCol * 8 + wn * 2 + (ntp >> 1);
            int r = wm * 64 + mt * 16 + gid;
            size_t base = ((size_t)bb * 128 + g * 4 + tig) * SEQ + m0;
            g_GQ[base + r] = packq(acc[mt][ntp][0], acc[mt][ntp][1],
                                   acc[mt][ntp + 1][0], acc[mt][ntp + 1][1]);
            g_GQ[base + r + 8] = packq(acc[mt][ntp][2], acc[mt][ntp][3],
                                       acc[mt][ntp + 1][2], acc[mt][ntp + 1][3]);
        }
}

// ---------------------------------------------------------------------------
// Kernel C: per (batch, quarter): S[64x256] = G_q @ X_b^T (fp16 mma, quads),
// row softmax, colsum -> w, y = w @ X_b.  256 thr = 8 warps (2x4),
// warp tile 32x64.  2 CTAs/SM (smem ~66KB, regs capped 128).
// ---------------------------------------------------------------------------
#define C_ST 2624   // b64 per stage: G 8*68 + X 8*260
__global__ void __launch_bounds__(256, 2) attn_kernel(float* __restrict__ Y4)
{
    uint2* sm = (uint2*)dynsmem;
    float* red  = dynsmem + 3 * C_ST * 2;      // [64][4]
    float* wcol = red + 64 * 4;                // [2][256]
    float* w_s  = wcol + 2 * 256;              // [256]

    int bx = blockIdx.x;           // 0..2047
    int b  = bx >> 2;
    int q  = bx & 3;
    int tid  = threadIdx.x;
    int warp = tid >> 5, lane = tid & 31;
    int wm = warp >> 2, wn = warp & 3;   // 2 x 4
    int gid = lane >> 2, tig = lane & 3;

    float acc[2][8][4];
#pragma unroll
    for (int mt = 0; mt < 2; mt++)
#pragma unroll
        for (int nt = 0; nt < 8; nt++)
#pragma unroll
            for (int r = 0; r < 4; r++) acc[mt][nt][r] = 0.0f;

    unsigned smb = sm_u32(sm);
    int gjr = tid >> 5, gmp = (tid & 31) * 2;      // G: 8 rows x 64 cols
    const uint2* GQb = g_GQ + (size_t)b * 128 * SEQ + q * 64;
    const uint2* XQb = g_XQ + (size_t)b * 128 * SEQ;

    auto issue = [&](int s, int i) {
        unsigned gb = smb + s * C_ST * 8;
        unsigned xb = gb + 8 * 68 * 8;
        cp16g(gb + (gjr * 68 + gmp) * 8, GQb + (size_t)(8 * i + gjr) * SEQ + gmp);
#pragma unroll
        for (int t = 0; t < 4; t++) {
            int id = tid + t * 256;
            int xjr = id >> 7, xmp = (id & 127) * 2;
            cp16g(xb + (xjr * 260 + xmp) * 8, XQb + (size_t)(8 * i + xjr) * SEQ + xmp);
        }
        CP_COMMIT();
    };

    const int NT = 16;
    issue(0, 0);
    issue(1, 1);

#pragma unroll
    for (int i = 0; i < NT; i++) {
        if (i + 1 < NT) CP_WAIT1(); else CP_WAIT0();
        __syncthreads();
        if (i + 2 < NT) issue((i + 2) % 3, i + 2);

        const uint2* G_s = sm + (i % 3) * C_ST;
        const uint2* X_s = G_s + 8 * 68;
#pragma unroll
        for (int gl = 0; gl < 2; gl++) {
            int jb = gl * 4 + tig;
            uint2 va[2], vb[2], w[8];
#pragma unroll
            for (int mt = 0; mt < 2; mt++) {
                int row = wm * 32 + mt * 16 + gid;
                va[mt] = G_s[jb * 68 + row];
                vb[mt] = G_s[jb * 68 + row + 8];
            }
#pragma unroll
            for (int nt = 0; nt < 8; nt++)
                w[nt] = X_s[jb * 260 + wn * 64 + nt * 8 + gid];
#pragma unroll
            for (int mt = 0; mt < 2; mt++)
#pragma unroll
                for (int nt = 0; nt < 8; nt++)
                    mma_f16(acc[mt][nt], va[mt].x, vb[mt].x, va[mt].y, vb[mt].y,
                            w[nt].x, w[nt].y);
        }
    }
    __syncthreads();

    // ---------------- softmax epilogue (rows 0..63) ----------------
    float rm[2][2];
#pragma unroll
    for (int mt = 0; mt < 2; mt++) {
        float m0 = -1e30f, m1 = -1e30f;
#pragma unroll
        for (int nt = 0; nt < 8; nt++) {
            m0 = fmaxf(m0, fmaxf(acc[mt][nt][0], acc[mt][nt][1]));
            m1 = fmaxf(m1, fmaxf(acc[mt][nt][2], acc[mt][nt][3]));
        }
        m0 = fmaxf(m0, __shfl_xor_sync(0xffffffffu, m0, 1));
        m0 = fmaxf(m0, __shfl_xor_sync(0xffffffffu, m0, 2));
        m1 = fmaxf(m1, __shfl_xor_sync(0xffffffffu, m1, 1));
        m1 = fmaxf(m1, __shfl_xor_sync(0xffffffffu, m1, 2));
        rm[mt][0] = m0; rm[mt][1] = m1;
    }
    if (tig == 0) {
#pragma unroll
        for (int mt = 0; mt < 2; mt++) {
            red[(wm * 32 + mt * 16 + gid) * 4 + wn]     = rm[mt][0];
            red[(wm * 32 + mt * 16 + gid + 8) * 4 + wn] = rm[mt][1];
        }
    }
    __syncthreads();
#pragma unroll
    for (int mt = 0; mt < 2; mt++) {
        int r0 = (wm * 32 + mt * 16 + gid) * 4;
        int r1 = r0 + 32;
        rm[mt][0] = fmaxf(fmaxf(red[r0], red[r0 + 1]), fmaxf(red[r0 + 2], red[r0 + 3]));
        rm[mt][1] = fmaxf(fmaxf(red[r1], red[r1 + 1]), fmaxf(red[r1 + 2], red[r1 + 3]));
    }
    __syncthreads();

    float rs[2][2];
#pragma unroll
    for (int mt = 0; mt < 2; mt++) {
        float s0 = 0.0f, s1 = 0.0f;
#pragma unroll
        for (int nt = 0; nt < 8; nt++) {
            acc[mt][nt][0] = __expf(acc[mt][nt][0] - rm[mt][0]);
            acc[mt][nt][1] = __expf(acc[mt][nt][1] - rm[mt][0]);
            acc[mt][nt][2] = __expf(acc[mt][nt][2] - rm[mt][1]);
            acc[mt][nt][3] = __expf(acc[mt][nt][3] - rm[mt][1]);
            s0 += acc[mt][nt][0] + acc[mt][nt][1];
            s1 += acc[mt][nt][2] + acc[mt][nt][3];
        }
        s0 += __shfl_xor_sync(0xffffffffu, s0, 1);
        s0 += __shfl_xor_sync(0xffffffffu, s0, 2);
        s1 += __shfl_xor_sync(0xffffffffu, s1, 1);
        s1 += __shfl_xor_sync(0xffffffffu, s1, 2);
        rs[mt][0] = s0; rs[mt][1] = s1;
    }
    if (tig == 0) {
#pragma unroll
        for (int mt = 0; mt < 2; mt++) {
            red[(wm * 32 + mt * 16 + gid) * 4 + wn]     = rs[mt][0];
            red[(wm * 32 + mt * 16 + gid + 8) * 4 + wn] = rs[mt][1];
        }
    }
    __syncthreads();
#pragma unroll
    for (int mt = 0; mt < 2; mt++) {
        int r0 = (wm * 32 + mt * 16 + gid) * 4;
        int r1 = r0 + 32;
        rs[mt][0] = 1.0f / (red[r0] + red[r0 + 1] + red[r0 + 2] + red[r0 + 3]);
        rs[mt][1] = 1.0f / (red[r1] + red[r1 + 1] + red[r1 + 2] + red[r1 + 3]);
    }

    float cp[8][2];
#pragma unroll
    for (int nt = 0; nt < 8; nt++) {
        cp[nt][0] = acc[0][nt][0] * rs[0][0] + acc[0][nt][2] * rs[0][1]
                  + acc[1][nt][0] * rs[1][0] + acc[1][nt][2] * rs[1][1];
        cp[nt][1] = acc[0][nt][1] * rs[0][0] + acc[0][nt][3] * rs[0][1]
                  + acc[1][nt][1] * rs[1][0] + acc[1][nt][3] * rs[1][1];
    }
#pragma unroll
    for (int nt = 0; nt < 8; nt++) {
#pragma unroll
        for (int o = 4; o < 32; o <<= 1) {
            cp[nt][0] += __shfl_xor_sync(0xffffffffu, cp[nt][0], o);
            cp[nt][1] += __shfl_xor_sync(0xffffffffu, cp[nt][1], o);
        }
    }
    if (gid == 0) {
#pragma unroll
        for (int nt = 0; nt < 8; nt++) {
            wcol[wm * 256 + wn * 64 + nt * 8 + 2 * tig]     = cp[nt][0];
            wcol[wm * 256 + wn * 64 + nt * 8 + 2 * tig + 1] = cp[nt][1];
        }
    }
    __syncthreads();
    w_s[tid] = wcol[tid] + wcol[256 + tid];
    __syncthreads();

    // ---------------- y epilogue (quad-native) ----------------
    // thread (r = tid>>1, p = tid&1): float4 for quad-row r over 128 m's,
    // reduce over p, p==0 writes 2 float2.
    {
        int r = tid >> 1, p = tid & 1;
        const uint2* Xq = XQb + (size_t)r * SEQ + p * 128;
        const float* wp = w_s + p * 128;
        float4 a = make_float4(0.f, 0.f, 0.f, 0.f);
#pragma unroll 8
        for (int m = 0; m < 128; m++) {
            uint2 qv = Xq[m];
            float wv = wp[m];
            __half2 lo = *reinterpret_cast<__half2*>(&qv.x);
            __half2 hi = *reinterpret_cast<__half2*>(&qv.y);
            float2 flo = __half22float2(lo);
            float2 fhi = __half22float2(hi);
            a.x = fmaf(wv, flo.x, a.x);
            a.y = fmaf(wv, flo.y, a.y);
            a.z = fmaf(wv, fhi.x, a.z);
            a.w = fmaf(wv, fhi.y, a.w);
        }
        a.x += __shfl_xor_sync(0xffffffffu, a.x, 1);
        a.y += __shfl_xor_sync(0xffffffffu, a.y, 1);
        a.z += __shfl_xor_sync(0xffffffffu, a.z, 1);
        a.w += __shfl_xor_sync(0xffffffffu, a.w, 1);
        if (p == 0) {
            int g = r >> 2, j = r & 3;
            int d0 = 16 * g + 2 * j;
            float* yp = Y4 + (size_t)bx * DIM;
            *(float2*)(yp + d0)     = make_float2(a.x, a.y);
            *(float2*)(yp + d0 + 8) = make_float2(a.z, a.w);
        }
    }
}

// ---------------------------------------------------------------------------
// Kernel D: merged = Y @ Wv, Y[b] = sum of 4 quarter partials.
// ---------------------------------------------------------------------------
__global__ void __launch_bounds__(256) final_gemm_kernel(const float* __restrict__ Wv,
                                                         float* __restrict__ out)
{
    __shared__ float As[32][68];
    __shared__ float Bs[32][68];
    int tid  = threadIdx.x;
    int batch0 = blockIdx.y * 64;
    int col0   = blockIdx.x * 64;

    int ar = tid >> 2, akk = (tid & 3) * 8;
    int bk = tid >> 3, bn = (tid & 7) * 8;
    int tr = tid >> 4, tc = tid & 15;

    float acc[4][4];
#pragma unroll
    for (int i = 0; i < 4; i++)
#pragma unroll
        for (int j = 0; j < 4; j++) acc[i][j] = 0.0f;

    for (int kt = 0; kt < DIM; kt += 32) {
        {
            const float* y0 = g_Y4 + (size_t)(4 * (batch0 + ar)) * DIM + kt + akk;
#pragma unroll
            for (int h = 0; h < 8; h += 4) {
                float4 v0 = *(const float4*)(y0 + h);
                float4 v1 = *(const float4*)(y0 + DIM + h);
                float4 v2 = *(const float4*)(y0 + 2 * DIM + h);
                float4 v3 = *(const float4*)(y0 + 3 * DIM + h);
                As[akk + h + 0][ar] = v0.x + v1.x + v2.x + v3.x;
                As[akk + h + 1][ar] = v0.y + v1.y + v2.y + v3.y;
                As[akk + h + 2][ar] = v0.z + v1.z + v2.z + v3.z;
                As[akk + h + 3][ar] = v0.w + v1.w + v2.w + v3.w;
            }
        }
        {
            const float* wp = Wv + (size_t)(kt + bk) * DIM + col0 + bn;
            *(float4*)(&Bs[bk][bn])     = *(const float4*)wp;
            *(float4*)(&Bs[bk][bn + 4]) = *(const float4*)(wp + 4);
        }
        __syncthreads();
#pragma unroll
        for (int k = 0; k < 32; k++) {
            float4 ra = *(const float4*)(&As[k][tr * 4]);
            float4 rb = *(const float4*)(&Bs[k][tc * 4]);
            float a[4] = {ra.x, ra.y, ra.z, ra.w};
            float b[4] = {rb.x, rb.y, rb.z, rb.w};
#pragma unroll
            for (int i = 0; i < 4; i++)
#pragma unroll
                for (int j = 0; j < 4; j++)
                    acc[i][j] += a[i] * b[j];
        }
        __syncthreads();
    }
#pragma unroll
    for (int i = 0; i < 4; i++) {
        float* op = out + (size_t)(batch0 + tr * 4 + i) * DIM + col0 + tc * 4;
        *(float4*)op = make_float4(acc[i][0], acc[i][1], acc[i][2], acc[i][3]);
    }
}

// ---------------------------------------------------------------------------
// Launch
// ---------------------------------------------------------------------------
extern "C" void kernel_launch(void* const* d_in, const int* in_sizes, int n_in,
                              void* d_out, int out_size)
{
    const float* X  = (const float*)d_in[0];   // [512,256,512]
    const float* Wq = (const float*)d_in[1];   // [512,512]
    const float* Wk = (const float*)d_in[2];
    const float* Wv = (const float*)d_in[3];
    float* out = (float*)d_out;                // [512,512]

    float* Y4;
    cudaGetSymbolAddress((void**)&Y4, g_Y4);

    const int smemB = 3 * B_ST * 8;                                 // 50688 B
    const int smemC = 3 * C_ST * 8 + (256 + 512 + 256) * 4;         // 67072 B
    cudaFuncSetAttribute(gemm_G_kernel, cudaFuncAttributeMaxDynamicSharedMemorySize, smemB);
    cudaFuncSetAttribute(attn_kernel,   cudaFuncAttributeMaxDynamicSharedMemorySize, smemC);

    // X -> quad-packed fp16
    x2h_kernel<<<dim3(8, 4, 512), 256>>>(X);
    // A: MQ = quad-pack(norm * Wq @ Wk^T)
    wqwk_kernel<<<dim3(8, 8), 256>>>(Wq, Wk);
    // B: GQ = quad-pack(X @ M)  (fp16 mma.sync)
    gemm_G_kernel<<<dim3(4, 1024), 256, smemB>>>();
    // C: fused scores/softmax/colsum/y per (batch, quarter)
    attn_kernel<<<2048, 256, smemC>>>(Y4);
    // D: merged = (sum of 4 quarters) @ Wv
    final_gemm_kernel<<<dim3(8, 8), 256>>>(Wv, out);
}